// round 4
// baseline (speedup 1.0000x reference)
#include <cuda_runtime.h>
#include <cuda_bf16.h>

// ConditionalCNF: B=524288 samples, scalar z, cond dim 8, 3-layer tanh MLP H=32,
// RK4 N_STEPS=20 over [0,1], augmented with exact divergence.
//
// Strategy: one thread per sample. Weights broadcast from shared memory.
// cond-dependent layer-1 preactivation hoisted out of the 80 evals.
// The two 32x32 matvecs per eval (h-path and d-path share W2 rows) are done
// with fma.rn.f32x2 packed over K-pairs: weights load pre-packed from shared.

static constexpr int H = 32;
static constexpr int C = 8;
static constexpr int DIN = 9;          // 1 + C
static constexpr int NSTEPS = 20;

__device__ __forceinline__ float tanh_fast(float x) {
    // tanh(x) = 1 - 2/(exp(2x)+1), via ex2.approx (2 ulp) + rcp.approx (1 ulp).
    // Saturates correctly at +/-inf. Rel err ~1e-6 << 1e-3 tolerance.
    float e;
    asm("ex2.approx.f32 %0, %1;" : "=f"(e) : "f"(x * 2.8853900817779268f));
    float r;
    asm("rcp.approx.f32 %0, %1;" : "=f"(r) : "f"(e + 1.0f));
    return fmaf(-2.0f, r, 1.0f);
}

__device__ __forceinline__ void fma2(unsigned long long& d,
                                     unsigned long long a,
                                     unsigned long long b) {
    asm("fma.rn.f32x2 %0, %1, %2, %3;" : "=l"(d) : "l"(a), "l"(b), "l"(d));
}

__device__ __forceinline__ unsigned long long pack2(float lo, float hi) {
    unsigned long long r;
    asm("mov.b64 %0, {%1, %2};" : "=l"(r) : "f"(lo), "f"(hi));
    return r;
}

__device__ __forceinline__ void unpack2(unsigned long long v, float& lo, float& hi) {
    asm("mov.b64 {%0, %1}, %2;" : "=f"(lo), "=f"(hi) : "l"(v));
}

__global__ void __launch_bounds__(128)
cnf_kernel(const float* __restrict__ T,
           const float* __restrict__ cond,
           const float* __restrict__ gW1,
           const float* __restrict__ gb1,
           const float* __restrict__ gW2,
           const float* __restrict__ gb2,
           const float* __restrict__ gW3,
           const float* __restrict__ gb3,
           float* __restrict__ out,
           int B)
{
    __shared__ __align__(16) float sW2[H * H];   // row-major, pairs contiguous
    __shared__ float sb2[H];
    __shared__ float sW3[H];
    __shared__ float sw10[H];                    // W1[:,0]
    __shared__ float sW1c[H * C];                // W1[:,1:9] row-major [j][c]
    __shared__ float sb1[H];

    const int tid = threadIdx.x;
    for (int i = tid; i < H * H; i += blockDim.x) sW2[i] = gW2[i];
    if (tid < H) {
        sb2[tid]  = gb2[tid];
        sW3[tid]  = gW3[tid];
        sw10[tid] = gW1[tid * DIN];
        sb1[tid]  = gb1[tid];
    }
    for (int i = tid; i < H * C; i += blockDim.x) {
        int j = i / C, c = i % C;
        sW1c[i] = gW1[j * DIN + 1 + c];
    }
    __syncthreads();

    const int idx = blockIdx.x * blockDim.x + tid;
    if (idx >= B) return;

    float z = T[idx];

    // cond row: 8 floats, 16B-aligned (idx*32 bytes)
    const float4* cptr = reinterpret_cast<const float4*>(cond) + idx * 2;
    float4 c0 = cptr[0];
    float4 c1 = cptr[1];
    float cc[C] = {c0.x, c0.y, c0.z, c0.w, c1.x, c1.y, c1.z, c1.w};

    // Hoisted layer-1 preactivation (cond part + bias), fixed for all 80 evals.
    float pre1[H];
#pragma unroll
    for (int j = 0; j < H; j++) {
        float s = sb1[j];
#pragma unroll
        for (int c = 0; c < C; c++) s = fmaf(cc[c], sW1c[j * C + c], s);
        pre1[j] = s;
    }

    const float b3v = gb3[0];
    const float dt = 1.0f / (float)NSTEPS;     // (T1 - T0)/N_STEPS
    const float dt6 = dt / 6.0f;
    float logp = 0.0f;

#pragma unroll 1
    for (int step = 0; step < NSTEPS; step++) {
        float zs = z;      // stage input
        float az = 0.0f;   // sum coef*kz
        float ad = 0.0f;   // sum coef*kd

#pragma unroll 1
        for (int st = 0; st < 4; st++) {
            // ---- eval: (kz, kd) = f(zs) ----
            unsigned long long h1p[H / 2];
            unsigned long long d1p[H / 2];
#pragma unroll
            for (int p = 0; p < H / 2; p++) {
                float w0 = sw10[2 * p];
                float w1 = sw10[2 * p + 1];
                float x0 = fmaf(zs, w0, pre1[2 * p]);
                float x1 = fmaf(zs, w1, pre1[2 * p + 1]);
                float h0 = tanh_fast(x0);
                float h1 = tanh_fast(x1);
                float g0 = fmaf(-h0, h0, 1.0f) * w0;
                float g1 = fmaf(-h1, h1, 1.0f) * w1;
                h1p[p] = pack2(h0, h1);
                d1p[p] = pack2(g0, g1);
            }

            float dz = 0.0f, dv = 0.0f;
#pragma unroll 8
            for (int j = 0; j < H; j++) {
                unsigned long long sacc = 0ull;  // {0.f, 0.f}
                unsigned long long tacc = 0ull;
                const ulonglong2* wrow =
                    reinterpret_cast<const ulonglong2*>(sW2 + j * H);
#pragma unroll
                for (int i2 = 0; i2 < H / 4; i2++) {
                    ulonglong2 w = wrow[i2];
                    fma2(sacc, w.x, h1p[2 * i2]);
                    fma2(tacc, w.x, d1p[2 * i2]);
                    fma2(sacc, w.y, h1p[2 * i2 + 1]);
                    fma2(tacc, w.y, d1p[2 * i2 + 1]);
                }
                float s0, s1, t0, t1;
                unpack2(sacc, s0, s1);
                unpack2(tacc, t0, t1);
                float s  = (s0 + s1) + sb2[j];
                float h2 = tanh_fast(s);
                float g2 = fmaf(-h2, h2, 1.0f);
                float w3 = sW3[j];
                dz = fmaf(w3, h2, dz);
                dv = fmaf(w3, g2 * (t0 + t1), dv);
            }
            float kz = dz + b3v;
            float kd = dv;
            // ---- RK4 accumulate ----
            float coef = (st == 1 || st == 2) ? 2.0f : 1.0f;
            az = fmaf(coef, kz, az);
            ad = fmaf(coef, kd, ad);
            float a = (st == 2) ? dt : (0.5f * dt);  // unused at st==3
            zs = fmaf(a, kz, z);
        }

        z    = fmaf(dt6, az, z);
        logp = fmaf(dt6, ad, logp);
    }

    out[idx]     = z;      // z_T
    out[B + idx] = logp;   // delta_logp
}

extern "C" void kernel_launch(void* const* d_in, const int* in_sizes, int n_in,
                              void* d_out, int out_size) {
    const float* T    = (const float*)d_in[0];
    const float* cond = (const float*)d_in[1];
    const float* W1   = (const float*)d_in[2];
    const float* b1   = (const float*)d_in[3];
    const float* W2   = (const float*)d_in[4];
    const float* b2   = (const float*)d_in[5];
    const float* W3   = (const float*)d_in[6];
    const float* b3   = (const float*)d_in[7];
    float* out = (float*)d_out;

    const int B = in_sizes[0];                 // 524288 (T is [B,1])
    const int threads = 128;
    const int blocks = (B + threads - 1) / threads;
    cnf_kernel<<<blocks, threads>>>(T, cond, W1, b1, W2, b2, W3, b3, out, B);
}